// round 7
// baseline (speedup 1.0000x reference)
#include <cuda_runtime.h>
#include <stdint.h>

// ============================================================================
// Colorization L2Loss, two kernels (fused/barrier variants measured slower).
//   loss = mean_b sum_{c,h,w} (in-tgt)^2 * prior[argmin_q d2(tgt_px, gamut[q])]
//
// Build (512x256, one warp per 64x64 cell): candidate set = bins with
//   d(center,bin) <= dmin(center)+diag (provable NN superset). Emits 16B/cell:
//   8 x u16 slots = candidate_index << 4 (pre-scaled LDS byte offsets, <=5008),
//   dup-padded; bit15(slot3) => >4 candidates (eval slots 4..7 too);
//   bit15(slot7) => >8 candidates (exact full scan, ~0.15% of cells).
// Loss (256x256, 4 px/thread): float4 I/O loads, ONE LDG.128 pack load,
//   4 (+4 on flag) shared-float4 candidate evals, exact strict-< argmin in
//   ascending index order (same tie-break as argmin). No global fallback path.
// ============================================================================

#define LGRID 64
#define NCELL (LGRID * LGRID)
#define MAXQ  320          // >= Q=313, exactly 10 warp-iterations
#define OVF4  0x80000000u  // bit15 of slot3 within pack.y
#define OVF8  0x80000000u  // bit15 of slot7 within pack.w

__device__ uint4 g_pack[NCELL];   // 64 KB candidate table

// ---------------------------------------------------------------------------
__global__ void __launch_bounds__(256) build_lut_kernel(
    const float2* __restrict__ gamut, const float* __restrict__ prior,
    float* __restrict__ out, int Q)
{
    __shared__ float4 sf[MAXQ];             // (-2gx, -2gy, |g|^2+16, prior)
    __shared__ unsigned short scand[8][8];  // first 8 candidates per warp

    for (int i = threadIdx.x; i < Q; i += 256) {
        const float2 g = gamut[i];
        sf[i] = make_float4(-2.0f * g.x, -2.0f * g.y,
                            fmaf(g.x, g.x, fmaf(g.y, g.y, 16.0f)),
                            prior[i]);
    }
    __syncthreads();

    if (blockIdx.x == 0 && threadIdx.x == 0) out[0] = 0.0f;

    const int warp = threadIdx.x >> 5;
    const int lane = threadIdx.x & 31;
    const int cell = blockIdx.x * 8 + warp;       // 512*8 = 4096 exactly

    const int ix = cell & (LGRID - 1);
    const int iy = cell >> 6;
    const float cellw = 2.0f / (float)LGRID;
    const float cx = -1.0f + ((float)ix + 0.5f) * cellw;
    const float cy = -1.0f + ((float)iy + 0.5f) * cellw;
    const float c2 = fmaf(cx, cx, cy * cy);
    const float diag = 0.04450f;                  // 0.044194 + FP pad

    // score = d2 + 16 - c2 (identical fma form to loss phase)
    float scv[MAXQ / 32];
    float smin = 1e30f;
    #pragma unroll
    for (int j = 0; j < MAXQ / 32; j++) {
        const int b = (j << 5) + lane;
        float sc = 1e30f;
        if (b < Q) {
            const float4 g = sf[b];
            sc = fmaf(g.x, cx, fmaf(g.y, cy, g.z));
        }
        scv[j] = sc;
        smin = fminf(smin, sc);
    }
    #pragma unroll
    for (int off = 16; off; off >>= 1)
        smin = fminf(smin, __shfl_xor_sync(0xFFFFFFFFu, smin, off));

    const float d2min = fmaxf(smin - 16.0f + c2, 0.0f);
    const float s     = sqrtf(d2min) + diag;
    const float thr   = fmaf(s, s, 16.0f - c2) + 2e-5f;

    int base = 0;
    #pragma unroll
    for (int j = 0; j < MAXQ / 32; j++) {
        const bool take = (scv[j] <= thr);
        const unsigned m = __ballot_sync(0xFFFFFFFFu, take);
        if (take) {
            const int pos = base + __popc(m & ((1u << lane) - 1u));
            if (pos < 8)
                scand[warp][pos] = (unsigned short)((j << 5) + lane);
        }
        base += __popc(m);
    }
    __syncwarp();

    if (lane == 0) {
        unsigned v[8];
        #pragma unroll
        for (int j = 0; j < 8; j++) {
            const int sel = (j < base) ? j : 0;            // base >= 1 always
            v[j] = ((unsigned)scand[warp][sel]) << 4;      // pre-scaled offset
        }
        uint4 p;
        p.x = v[0] | (v[1] << 16);
        p.y = v[2] | (v[3] << 16);
        p.z = v[4] | (v[5] << 16);
        p.w = v[6] | (v[7] << 16);
        if (base > 4) p.y |= OVF4;
        if (base > 8) p.w |= OVF8;
        g_pack[cell] = p;
    }
}

// ---------------------------------------------------------------------------
__global__ void __launch_bounds__(256) loss_kernel(
    const float*  __restrict__ input,
    const float*  __restrict__ target,
    const float2* __restrict__ gamut,
    const float*  __restrict__ prior,
    float*        __restrict__ out,
    int Q)
{
    __shared__ float4 sf[MAXQ];            // (-2gx, -2gy, |g|^2+16, prior)
    __shared__ float  ws[8];

    for (int i = threadIdx.x; i < Q; i += 256) {
        const float2 g = gamut[i];
        sf[i] = make_float4(-2.0f * g.x, -2.0f * g.y,
                            fmaf(g.x, g.x, fmaf(g.y, g.y, 16.0f)),
                            prior[i]);
    }
    __syncthreads();

    const char* sfb = (const char*)sf;
    const int tid   = blockIdx.x * 256 + threadIdx.x;    // 0..65535
    const int q     = tid << 2;
    const int bb    = q >> 16;
    const int n     = q & 65535;
    const int base0 = bb * 131072 + n;

    const float4 tv0 = *(const float4*)(target + base0);
    const float4 tv1 = *(const float4*)(target + base0 + 65536);
    const float4 iv0 = *(const float4*)(input  + base0);
    const float4 iv1 = *(const float4*)(input  + base0 + 65536);

    const float ta[4] = {tv0.x, tv0.y, tv0.z, tv0.w};
    const float tb[4] = {tv1.x, tv1.y, tv1.z, tv1.w};
    const float ia[4] = {iv0.x, iv0.y, iv0.z, iv0.w};
    const float ib[4] = {iv1.x, iv1.y, iv1.z, iv1.w};

    float acc = 0.0f;

    #pragma unroll
    for (int k = 0; k < 4; k++) {
        const float t0 = ta[k], t1 = tb[k];
        // clamp-free cell: t in [-1,1] -> [0, 63.999]; slop covered by pad
        const int ix = (int)((t0 + 1.0f) * 31.9995f);
        const int iy = (int)((t1 + 1.0f) * 31.9995f);
        const int cc = (iy << 6) | ix;

        const uint4 p = g_pack[cc];

        float4 g;
        float  sc, bestSc, bestW;

        g = *(const float4*)(sfb + (p.x & 0x7FF0u));
        bestSc = fmaf(g.x, t0, fmaf(g.y, t1, g.z));
        bestW  = g.w;
        g = *(const float4*)(sfb + ((p.x >> 16) & 0x7FF0u));
        sc = fmaf(g.x, t0, fmaf(g.y, t1, g.z));
        if (sc < bestSc) { bestSc = sc; bestW = g.w; }
        g = *(const float4*)(sfb + (p.y & 0x7FF0u));
        sc = fmaf(g.x, t0, fmaf(g.y, t1, g.z));
        if (sc < bestSc) { bestSc = sc; bestW = g.w; }
        g = *(const float4*)(sfb + ((p.y >> 16) & 0x7FF0u));
        sc = fmaf(g.x, t0, fmaf(g.y, t1, g.z));
        if (sc < bestSc) { bestSc = sc; bestW = g.w; }

        if (p.y & OVF4) {                      // >4 candidates: 4 more, in smem
            g = *(const float4*)(sfb + (p.z & 0x7FF0u));
            sc = fmaf(g.x, t0, fmaf(g.y, t1, g.z));
            if (sc < bestSc) { bestSc = sc; bestW = g.w; }
            g = *(const float4*)(sfb + ((p.z >> 16) & 0x7FF0u));
            sc = fmaf(g.x, t0, fmaf(g.y, t1, g.z));
            if (sc < bestSc) { bestSc = sc; bestW = g.w; }
            g = *(const float4*)(sfb + (p.w & 0x7FF0u));
            sc = fmaf(g.x, t0, fmaf(g.y, t1, g.z));
            if (sc < bestSc) { bestSc = sc; bestW = g.w; }
            g = *(const float4*)(sfb + ((p.w >> 16) & 0x7FF0u));
            sc = fmaf(g.x, t0, fmaf(g.y, t1, g.z));
            if (sc < bestSc) { bestSc = sc; bestW = g.w; }

            if (p.w & OVF8) {                  // >8 (~0.15% cells): exact scan
                bestSc = 1e30f;
                for (int bi = 0; bi < Q; bi++) {
                    const float4 gg = sf[bi];
                    sc = fmaf(gg.x, t0, fmaf(gg.y, t1, gg.z));
                    if (sc < bestSc) { bestSc = sc; bestW = gg.w; }
                }
            }
        }

        const float d0 = ia[k] - t0;
        const float d1 = ib[k] - t1;
        acc += bestW * fmaf(d0, d0, d1 * d1);
    }

    acc *= 0.25f;   // mean over batch b = 4

    #pragma unroll
    for (int off = 16; off; off >>= 1)
        acc += __shfl_xor_sync(0xFFFFFFFFu, acc, off);

    if ((threadIdx.x & 31) == 0) ws[threadIdx.x >> 5] = acc;
    __syncthreads();
    if (threadIdx.x < 8) {
        float v = ws[threadIdx.x];
        #pragma unroll
        for (int off = 4; off; off >>= 1)
            v += __shfl_xor_sync(0xFFu, v, off);
        if (threadIdx.x == 0) atomicAdd(out, v);
    }
}

// ---------------------------------------------------------------------------
extern "C" void kernel_launch(void* const* d_in, const int* in_sizes, int n_in,
                              void* d_out, int out_size)
{
    const float*  input  = (const float*)d_in[0];
    const float*  target = (const float*)d_in[1];
    const float2* gamut  = (const float2*)d_in[2];   // [Q,2]
    const float*  prior  = (const float*)d_in[3];    // [Q]
    float* out = (float*)d_out;
    const int Q = in_sizes[3];                        // 313

    // build LUT (also zeroes out[0]); then loss
    build_lut_kernel<<<NCELL / 8, 256>>>(gamut, prior, out, Q);
    loss_kernel<<<256, 256>>>(input, target, gamut, prior, out, Q);
}

// round 8
// speedup vs baseline: 1.3928x; 1.3928x over previous
#include <cuda_runtime.h>
#include <stdint.h>

// ============================================================================
// Colorization L2Loss, two kernels (R2 structure = measured-best loss kernel,
// rebalanced grid + lean build).
//   loss = mean_b sum_{c,h,w} (in-tgt)^2 * prior[argmin_q d2(tgt_px, gamut[q])]
//
// Build (512 x 256, one warp per 64x64 cell): candidates = bins with
//   d(center,bin) <= dmin(center)+diag  (provable NN superset of the cell).
//   Emits u64/cell: 4 x u16 indices dup-padded (ascending); slot3 sentinel
//   0xFFFF => overflow, full list in g_cand/g_cnt (written only then).
// Loss (512 x 128, 4 px/thread = 262144 px): float4 I/O, one u64 pack load,
//   4 shared-float4 evals, exact strict-< argmin (ascending index order =
//   argmin tie-break), rare global-list fallback. 512 blocks balance across
//   148 SMs with a 4:3 tail (vs 2:1 at 256 blocks).
// ============================================================================

#define LGRID 64
#define NCELL (LGRID * LGRID)
#define CAP   32
#define MAXQ  320          // >= Q=313, exactly 10 warp-iterations

__device__ unsigned long long g_pack[NCELL];    // 32 KB
__device__ unsigned short     g_cand[NCELL * CAP];
__device__ unsigned int       g_cnt[NCELL];

// ---------------------------------------------------------------------------
__global__ void __launch_bounds__(256) build_lut_kernel(
    const float2* __restrict__ gamut, float* __restrict__ out, int Q)
{
    __shared__ float2 sg[MAXQ];
    __shared__ unsigned short scand[8][CAP];

    for (int i = threadIdx.x; i < Q; i += 256) sg[i] = gamut[i];
    __syncthreads();

    if (blockIdx.x == 0 && threadIdx.x == 0) out[0] = 0.0f;

    const int warp = threadIdx.x >> 5;
    const int lane = threadIdx.x & 31;
    const int cell = blockIdx.x * 8 + warp;       // 512*8 = 4096 exactly

    const int ix = cell & (LGRID - 1);
    const int iy = cell >> 6;
    const float cellw = 2.0f / (float)LGRID;
    const float cx = -1.0f + ((float)ix + 0.5f) * cellw;
    const float cy = -1.0f + ((float)iy + 0.5f) * cellw;
    const float diag = 0.04450f;                  // 0.044194 + FP pad

    float d2v[MAXQ / 32];
    float dmin = 1e30f;
    #pragma unroll
    for (int j = 0; j < MAXQ / 32; j++) {
        const int b = (j << 5) + lane;
        float d2 = 1e30f;
        if (b < Q) {
            const float dx = sg[b].x - cx;
            const float dy = sg[b].y - cy;
            d2 = fmaf(dx, dx, dy * dy);
        }
        d2v[j] = d2;
        dmin = fminf(dmin, d2);
    }
    #pragma unroll
    for (int off = 16; off; off >>= 1)
        dmin = fminf(dmin, __shfl_xor_sync(0xFFFFFFFFu, dmin, off));

    const float s   = sqrtf(dmin) + diag;
    const float thr = fmaf(s, s, 1e-6f) * 1.00002f;

    int base = 0;
    #pragma unroll
    for (int j = 0; j < MAXQ / 32; j++) {
        const bool take = (d2v[j] <= thr);
        const unsigned m = __ballot_sync(0xFFFFFFFFu, take);
        if (take) {
            const int pos = base + __popc(m & ((1u << lane) - 1u));
            if (pos < CAP)
                scand[warp][pos] = (unsigned short)((j << 5) + lane);
        }
        base += __popc(m);
    }
    __syncwarp();

    if (base > 4) {                               // overflow list only if needed
        const int nw = min(base, CAP);
        for (int j = lane; j < nw; j += 32)
            g_cand[cell * CAP + j] = scand[warp][j];
        if (lane == 0) g_cnt[cell] = (unsigned)base;
    }
    if (lane == 0) {
        const unsigned long long i0 = scand[warp][0];      // base >= 1 always
        const unsigned long long i1 = (base > 1) ? scand[warp][1] : i0;
        const unsigned long long i2 = (base > 2) ? scand[warp][2] : i0;
        unsigned long long i3       = (base > 3) ? scand[warp][3] : i0;
        if (base > 4) i3 = 0xFFFFull;                      // overflow sentinel
        g_pack[cell] = i0 | (i1 << 16) | (i2 << 32) | (i3 << 48);
    }
}

// ---------------------------------------------------------------------------
// 512 blocks x 128 threads, 4 consecutive pixels per thread.
// Layout [b, 2, 256, 256]: pixel q -> b=q>>16, n=q&65535; ch0 at b*131072+n,
// ch1 at +65536. n%4==0 per thread -> float4 aligned.
// ---------------------------------------------------------------------------
__global__ void __launch_bounds__(128) loss_kernel(
    const float*  __restrict__ input,
    const float*  __restrict__ target,
    const float2* __restrict__ gamut,
    const float*  __restrict__ prior,
    float*        __restrict__ out,
    int Q)
{
    __shared__ float4 sf[MAXQ];   // (-2gx, -2gy, |g|^2+16, prior)
    __shared__ float  ws[4];

    for (int i = threadIdx.x; i < Q; i += 128) {
        const float2 g = gamut[i];
        sf[i] = make_float4(-2.0f * g.x, -2.0f * g.y,
                            fmaf(g.x, g.x, fmaf(g.y, g.y, 16.0f)),
                            prior[i]);
    }
    __syncthreads();

    const int tid   = blockIdx.x * 128 + threadIdx.x;   // 0..65535
    const int q     = tid << 2;
    const int bb    = q >> 16;
    const int n     = q & 65535;
    const int base0 = bb * 131072 + n;

    const float4 tv0 = *(const float4*)(target + base0);
    const float4 tv1 = *(const float4*)(target + base0 + 65536);
    const float4 iv0 = *(const float4*)(input  + base0);
    const float4 iv1 = *(const float4*)(input  + base0 + 65536);

    const float ta[4] = {tv0.x, tv0.y, tv0.z, tv0.w};
    const float tb[4] = {tv1.x, tv1.y, tv1.z, tv1.w};
    const float ia[4] = {iv0.x, iv0.y, iv0.z, iv0.w};
    const float ib[4] = {iv1.x, iv1.y, iv1.z, iv1.w};

    float acc = 0.0f;

    #pragma unroll
    for (int k = 0; k < 4; k++) {
        const float t0 = ta[k], t1 = tb[k];
        // clamp-free cell: t in [-1,1] -> [0, 63.999]; slop covered by pad
        const int ix = (int)((t0 + 1.0f) * 31.9995f);
        const int iy = (int)((t1 + 1.0f) * 31.9995f);
        const int cc = (iy << 6) | ix;

        const unsigned long long p = g_pack[cc];
        const unsigned a0 = (unsigned)(p & 0xFFFFull);
        const unsigned a1 = (unsigned)((p >> 16) & 0xFFFFull);
        const unsigned a2 = (unsigned)((p >> 32) & 0xFFFFull);
        const unsigned a3 = (unsigned)(p >> 48);

        float    bestSc;
        unsigned bestIdx;

        if (a3 != 0xFFFFu) {
            float4 g = sf[a0];
            bestSc  = fmaf(g.x, t0, fmaf(g.y, t1, g.z));
            bestIdx = a0;
            g = sf[a1];
            float s1 = fmaf(g.x, t0, fmaf(g.y, t1, g.z));
            if (s1 < bestSc) { bestSc = s1; bestIdx = a1; }
            g = sf[a2];
            float s2 = fmaf(g.x, t0, fmaf(g.y, t1, g.z));
            if (s2 < bestSc) { bestSc = s2; bestIdx = a2; }
            g = sf[a3];
            float s3 = fmaf(g.x, t0, fmaf(g.y, t1, g.z));
            if (s3 < bestSc) { bestSc = s3; bestIdx = a3; }
        } else {
            bestSc = 1e30f; bestIdx = 0;
            const unsigned cnt = g_cnt[cc];
            if (cnt <= CAP) {
                const unsigned short* cl = &g_cand[cc * CAP];
                for (unsigned j = 0; j < cnt; j++) {
                    const unsigned bi = (unsigned)cl[j];
                    const float4 g = sf[bi];
                    const float sc = fmaf(g.x, t0, fmaf(g.y, t1, g.z));
                    if (sc < bestSc) { bestSc = sc; bestIdx = bi; }
                }
            } else {
                for (int bi = 0; bi < Q; bi++) {
                    const float4 g = sf[bi];
                    const float sc = fmaf(g.x, t0, fmaf(g.y, t1, g.z));
                    if (sc < bestSc) { bestSc = sc; bestIdx = (unsigned)bi; }
                }
            }
        }

        const float w  = sf[bestIdx].w;
        const float d0 = ia[k] - t0;
        const float d1 = ib[k] - t1;
        acc += w * fmaf(d0, d0, d1 * d1);
    }

    acc *= 0.25f;   // mean over batch b = 4

    #pragma unroll
    for (int off = 16; off; off >>= 1)
        acc += __shfl_xor_sync(0xFFFFFFFFu, acc, off);

    if ((threadIdx.x & 31) == 0) ws[threadIdx.x >> 5] = acc;
    __syncthreads();
    if (threadIdx.x < 4) {
        float v = ws[threadIdx.x];
        v += __shfl_xor_sync(0xFu, v, 2);
        v += __shfl_xor_sync(0xFu, v, 1);
        if (threadIdx.x == 0) atomicAdd(out, v);
    }
}

// ---------------------------------------------------------------------------
extern "C" void kernel_launch(void* const* d_in, const int* in_sizes, int n_in,
                              void* d_out, int out_size)
{
    const float*  input  = (const float*)d_in[0];
    const float*  target = (const float*)d_in[1];
    const float2* gamut  = (const float2*)d_in[2];   // [Q,2]
    const float*  prior  = (const float*)d_in[3];    // [Q]
    float* out = (float*)d_out;
    const int Q = in_sizes[3];                        // 313

    build_lut_kernel<<<NCELL / 8, 256>>>(gamut, out, Q);
    loss_kernel<<<512, 128>>>(input, target, gamut, prior, out, Q);
}

// round 9
// speedup vs baseline: 1.4199x; 1.0195x over previous
#include <cuda_runtime.h>
#include <stdint.h>

// ============================================================================
// Colorization L2Loss, two kernels.
//   loss = mean_b sum_{c,h,w} (in-tgt)^2 * prior[argmin_q d2(tgt_px, gamut[q])]
//
// Build (512x256, one warp per 64x64 cell over [-1,1]^2): candidates = bins
//   with d(center,bin) <= dmin(center)+diag (provable NN superset). Emits
//   u64/cell: 4 x u16 indices dup-padded (ascending); slot3 sentinel 0xFFFF =>
//   overflow, full list in g_cand/g_cnt (written only for such cells).
// Loss (512x256, 2 px/thread): copies the 32KB pack table + 5KB gamut table
//   into SHARED memory first, so the per-pixel chain is all-smem:
//   t-load -> LDS.64 pack -> 4x LDS.128 candidate evals -> fma/select.
//   Exact strict-< argmin in ascending index order (= argmin tie-break).
// ============================================================================

#define LGRID 64
#define NCELL (LGRID * LGRID)
#define CAP   32
#define MAXQ  320          // >= Q=313, exactly 10 warp-iterations

__device__ unsigned long long g_pack[NCELL];    // 32 KB
__device__ unsigned short     g_cand[NCELL * CAP];
__device__ unsigned int       g_cnt[NCELL];

// ---------------------------------------------------------------------------
__global__ void __launch_bounds__(256) build_lut_kernel(
    const float2* __restrict__ gamut, float* __restrict__ out, int Q)
{
    __shared__ float2 sg[MAXQ];
    __shared__ unsigned short scand[8][CAP];

    for (int i = threadIdx.x; i < Q; i += 256) sg[i] = gamut[i];
    __syncthreads();

    if (blockIdx.x == 0 && threadIdx.x == 0) out[0] = 0.0f;

    const int warp = threadIdx.x >> 5;
    const int lane = threadIdx.x & 31;
    const int cell = blockIdx.x * 8 + warp;       // 512*8 = 4096 exactly

    const int ix = cell & (LGRID - 1);
    const int iy = cell >> 6;
    const float cellw = 2.0f / (float)LGRID;
    const float cx = -1.0f + ((float)ix + 0.5f) * cellw;
    const float cy = -1.0f + ((float)iy + 0.5f) * cellw;
    const float diag = 0.04450f;                  // 0.044194 + FP pad

    float d2v[MAXQ / 32];
    float dmin = 1e30f;
    #pragma unroll
    for (int j = 0; j < MAXQ / 32; j++) {
        const int b = (j << 5) + lane;
        float d2 = 1e30f;
        if (b < Q) {
            const float dx = sg[b].x - cx;
            const float dy = sg[b].y - cy;
            d2 = fmaf(dx, dx, dy * dy);
        }
        d2v[j] = d2;
        dmin = fminf(dmin, d2);
    }
    #pragma unroll
    for (int off = 16; off; off >>= 1)
        dmin = fminf(dmin, __shfl_xor_sync(0xFFFFFFFFu, dmin, off));

    const float s   = sqrtf(dmin) + diag;
    const float thr = fmaf(s, s, 1e-6f) * 1.00002f;

    int base = 0;
    #pragma unroll
    for (int j = 0; j < MAXQ / 32; j++) {
        const bool take = (d2v[j] <= thr);
        const unsigned m = __ballot_sync(0xFFFFFFFFu, take);
        if (take) {
            const int pos = base + __popc(m & ((1u << lane) - 1u));
            if (pos < CAP)
                scand[warp][pos] = (unsigned short)((j << 5) + lane);
        }
        base += __popc(m);
    }
    __syncwarp();

    if (base > 4) {                               // overflow list only if needed
        const int nw = min(base, CAP);
        for (int j = lane; j < nw; j += 32)
            g_cand[cell * CAP + j] = scand[warp][j];
        if (lane == 0) g_cnt[cell] = (unsigned)base;
    }
    if (lane == 0) {
        const unsigned long long i0 = scand[warp][0];      // base >= 1 always
        const unsigned long long i1 = (base > 1) ? scand[warp][1] : i0;
        const unsigned long long i2 = (base > 2) ? scand[warp][2] : i0;
        unsigned long long i3       = (base > 3) ? scand[warp][3] : i0;
        if (base > 4) i3 = 0xFFFFull;                      // overflow sentinel
        g_pack[cell] = i0 | (i1 << 16) | (i2 << 32) | (i3 << 48);
    }
}

// ---------------------------------------------------------------------------
// Loss: 512 blocks x 256 threads, 2 consecutive pixels/thread (262144 px).
// Pack table + gamut table both in shared memory (all-smem pixel chain).
// ---------------------------------------------------------------------------
__global__ void __launch_bounds__(256) loss_kernel(
    const float*  __restrict__ input,
    const float*  __restrict__ target,
    const float2* __restrict__ gamut,
    const float*  __restrict__ prior,
    float*        __restrict__ out,
    int Q)
{
    __shared__ unsigned long long spack[NCELL];   // 32 KB
    __shared__ float4 sf[MAXQ];                   // 5 KB (-2gx,-2gy,|g|^2+16,w)
    __shared__ float  ws[8];

    // copy pack table: 4096 u64 = 2048 uint4; 256 threads -> 8 iters
    {
        const uint4* src = (const uint4*)g_pack;
        uint4* dst = (uint4*)spack;
        #pragma unroll
        for (int j = 0; j < 8; j++)
            dst[threadIdx.x + j * 256] = src[threadIdx.x + j * 256];
    }
    for (int i = threadIdx.x; i < Q; i += 256) {
        const float2 g = gamut[i];
        sf[i] = make_float4(-2.0f * g.x, -2.0f * g.y,
                            fmaf(g.x, g.x, fmaf(g.y, g.y, 16.0f)),
                            prior[i]);
    }
    __syncthreads();

    const int tid   = blockIdx.x * 256 + threadIdx.x;   // 0..131071
    const int q     = tid << 1;
    const int bb    = q >> 16;
    const int n     = q & 65535;
    const int base0 = bb * 131072 + n;

    const float2 tv0 = *(const float2*)(target + base0);
    const float2 tv1 = *(const float2*)(target + base0 + 65536);
    const float2 iv0 = *(const float2*)(input  + base0);
    const float2 iv1 = *(const float2*)(input  + base0 + 65536);

    const float ta[2] = {tv0.x, tv0.y};
    const float tb[2] = {tv1.x, tv1.y};
    const float ia[2] = {iv0.x, iv0.y};
    const float ib[2] = {iv1.x, iv1.y};

    float acc = 0.0f;

    #pragma unroll
    for (int k = 0; k < 2; k++) {
        const float t0 = ta[k], t1 = tb[k];
        // clamp-free cell: t in [-1,1] -> [0, 63.999]; slop covered by pad
        const int ix = (int)((t0 + 1.0f) * 31.9995f);
        const int iy = (int)((t1 + 1.0f) * 31.9995f);
        const int cc = (iy << 6) | ix;

        const unsigned long long p = spack[cc];
        const unsigned a0 = (unsigned)(p & 0xFFFFull);
        const unsigned a1 = (unsigned)((p >> 16) & 0xFFFFull);
        const unsigned a2 = (unsigned)((p >> 32) & 0xFFFFull);
        const unsigned a3 = (unsigned)(p >> 48);

        float    bestSc;
        unsigned bestIdx;

        if (a3 != 0xFFFFu) {
            float4 g = sf[a0];
            bestSc  = fmaf(g.x, t0, fmaf(g.y, t1, g.z));
            bestIdx = a0;
            g = sf[a1];
            float s1 = fmaf(g.x, t0, fmaf(g.y, t1, g.z));
            if (s1 < bestSc) { bestSc = s1; bestIdx = a1; }
            g = sf[a2];
            float s2 = fmaf(g.x, t0, fmaf(g.y, t1, g.z));
            if (s2 < bestSc) { bestSc = s2; bestIdx = a2; }
            g = sf[a3];
            float s3 = fmaf(g.x, t0, fmaf(g.y, t1, g.z));
            if (s3 < bestSc) { bestSc = s3; bestIdx = a3; }
        } else {
            // rare overflow cell: exact scan of the global list
            bestSc = 1e30f; bestIdx = 0;
            const unsigned cnt = g_cnt[cc];
            if (cnt <= CAP) {
                const unsigned short* cl = &g_cand[cc * CAP];
                for (unsigned j = 0; j < cnt; j++) {
                    const unsigned bi = (unsigned)cl[j];
                    const float4 g = sf[bi];
                    const float sc = fmaf(g.x, t0, fmaf(g.y, t1, g.z));
                    if (sc < bestSc) { bestSc = sc; bestIdx = bi; }
                }
            } else {
                for (int bi = 0; bi < Q; bi++) {
                    const float4 g = sf[bi];
                    const float sc = fmaf(g.x, t0, fmaf(g.y, t1, g.z));
                    if (sc < bestSc) { bestSc = sc; bestIdx = (unsigned)bi; }
                }
            }
        }

        const float w  = sf[bestIdx].w;
        const float d0 = ia[k] - t0;
        const float d1 = ib[k] - t1;
        acc += w * fmaf(d0, d0, d1 * d1);
    }

    acc *= 0.25f;   // mean over batch b = 4

    #pragma unroll
    for (int off = 16; off; off >>= 1)
        acc += __shfl_xor_sync(0xFFFFFFFFu, acc, off);

    if ((threadIdx.x & 31) == 0) ws[threadIdx.x >> 5] = acc;
    __syncthreads();
    if (threadIdx.x < 8) {
        float v = ws[threadIdx.x];
        #pragma unroll
        for (int off = 4; off; off >>= 1)
            v += __shfl_xor_sync(0xFFu, v, off);
        if (threadIdx.x == 0) atomicAdd(out, v);
    }
}

// ---------------------------------------------------------------------------
extern "C" void kernel_launch(void* const* d_in, const int* in_sizes, int n_in,
                              void* d_out, int out_size)
{
    const float*  input  = (const float*)d_in[0];
    const float*  target = (const float*)d_in[1];
    const float2* gamut  = (const float2*)d_in[2];   // [Q,2]
    const float*  prior  = (const float*)d_in[3];    // [Q]
    float* out = (float*)d_out;
    const int Q = in_sizes[3];                        // 313

    build_lut_kernel<<<NCELL / 8, 256>>>(gamut, out, Q);
    loss_kernel<<<512, 256>>>(input, target, gamut, prior, out, Q);
}